// round 9
// baseline (speedup 1.0000x reference)
#include <cuda_runtime.h>
#include <cuda_bf16.h>
#include <math.h>
#include <stdint.h>

// B=8, N=64, D=64, E=32. GEMM view: (32768 x 32) @ (32 x 4096), fused
// relu/mask/reduce epilogue + GRU tail. mma.sync m16n8k16 bf16 (HMMA),
// 3-term hi/lo split. 512-thread blocks / 64-reg budget -> 32 warps/SM
// for latency hiding (R8 was latency-bound at 16 warps/SM).

typedef unsigned int u32;

// W fragment buffer: [ig(64)][nt(8)][term(2)][lane(32)] uint4
__device__ uint4 g_Wfrag4[32768];   // 512 KB

static __device__ __forceinline__ void split2(float v0, float v1, u32& hi, u32& lo) {
    __nv_bfloat16 h0 = __float2bfloat16(v0);
    __nv_bfloat16 h1 = __float2bfloat16(v1);
    __nv_bfloat16 l0 = __float2bfloat16(v0 - __bfloat162float(h0));
    __nv_bfloat16 l1 = __float2bfloat16(v1 - __bfloat162float(h1));
    hi = ((u32)__bfloat16_as_ushort(h1) << 16) | (u32)__bfloat16_as_ushort(h0);
    lo = ((u32)__bfloat16_as_ushort(l1) << 16) | (u32)__bfloat16_as_ushort(l0);
}

#define MMA16816(c0,c1,c2,c3,a0,a1,a2,a3,b0,b1) \
    asm volatile("mma.sync.aligned.m16n8k16.row.col.f32.bf16.bf16.f32 " \
        "{%0,%1,%2,%3},{%4,%5,%6,%7},{%8,%9},{%0,%1,%2,%3};" \
        : "+f"(c0),"+f"(c1),"+f"(c2),"+f"(c3) \
        : "r"(a0),"r"(a1),"r"(a2),"r"(a3),"r"(b0),"r"(b1))

// ---------------- converter: W_e -> bf16 hi/lo fragments ----------------
__global__ void conv_w_kernel(const float* __restrict__ W_e) {
    int qg = blockIdx.x;                 // k-pair 0..15
    int kt = qg >> 3, h = (qg >> 2) & 1, q = qg & 3;
    int k0 = qg * 2;
    u32* W = (u32*)g_Wfrag4;
    int col = blockIdx.y * 1024 + threadIdx.x;
    #pragma unroll
    for (int u = 0; u < 4; u++, col += 256) {
        float w0 = W_e[(size_t)k0 * 4096 + col];
        float w1 = W_e[(size_t)(k0 + 1) * 4096 + col];
        u32 hi, lo; split2(w0, w1, hi, lo);
        int ig = col >> 6, nt = (col >> 3) & 7, n = col & 7;
        int base = ((((ig * 8 + nt) * 2 + 0) * 8 + n) * 4 + q) * 4 + kt * 2 + h;
        W[base]       = hi;
        W[base + 128] = lo;
    }
}

// ---------------- main kernel ----------------
// dynamic smem layout (bytes)
#define OFF_AF    0        // A frags: [mt(8)][kt(2)][term(2)][lane(32)] uint4 = 16KB
#define OFF_WF    16384    // wt frags: [mt(8)][nt(8)][lane(32)] float4 = 32KB
#define OFF_AGGS  49152    // 128 f
#define OFF_XROW  49664    // 128 f
#define OFF_XK1   50176    // 192 f
#define OFF_H1    50944    // 64 f
#define OFF_XK2   51200    // 192 f
#define OFF_HK2   51968    // 192 f
#define SMEM_SZ   52736

__global__ __launch_bounds__(512, 2) void mp_mma_kernel(
    const float* __restrict__ nodes,   // (8,64,64)
    const float* __restrict__ edges,   // (8,4096,32)
    const float* __restrict__ mask,    // (8,4096,1)
    const float* __restrict__ b_e,     // (4096,)
    const float* __restrict__ Kmat,    // (64,192)
    const float* __restrict__ Rmat,    // (64,192)
    const float* __restrict__ gbias,   // (2,192)
    float* __restrict__ out)           // (8,64,64)
{
    extern __shared__ char sm[];
    u32*    AF   = (u32*)(sm + OFF_AF);
    uint4*  AF4  = (uint4*)(sm + OFF_AF);
    float4* WF4  = (float4*)(sm + OFF_WF);
    float*  aggs = (float*)(sm + OFF_AGGS);
    float*  xrow = (float*)(sm + OFF_XROW);
    float*  xk1  = (float*)(sm + OFF_XK1);
    float*  h1   = (float*)(sm + OFF_H1);
    float*  xk2  = (float*)(sm + OFF_XK2);
    float*  hk2  = (float*)(sm + OFF_HK2);

    const int t    = threadIdx.x;
    const int lane = t & 31;
    const int wid  = t >> 5;          // 0..15
    const int b    = blockIdx.x >> 5;
    const int pair = blockIdx.x & 31;

    if (t < 128)
        xrow[t] = nodes[((size_t)b * 64 + pair * 2 + (t >> 6)) * 64 + (t & 63)];

    // ---- A conversion: edges rows -> fragment-major hi/lo in smem ----
    {
        int m = t >> 2, qtr = t & 3;              // quarter-row per thread
        int mt = m >> 4, r16 = m & 15, rr = r16 & 7;
        const float* ar = edges + ((size_t)(b * 4096 + pair * 128 + m)) * 32 + qtr * 8;
        float v[8];
        float4 x0 = *(const float4*)(ar);
        float4 x1 = *(const float4*)(ar + 4);
        v[0]=x0.x; v[1]=x0.y; v[2]=x0.z; v[3]=x0.w;
        v[4]=x1.x; v[5]=x1.y; v[6]=x1.z; v[7]=x1.w;
        #pragma unroll
        for (int i = 0; i < 8; i += 2) {
            int qg = qtr * 4 + (i >> 1);          // global k-pair 0..15
            int kt = qg >> 3, ql = qg & 7;
            int q = ql & 3, h = ql >> 2;
            int reg = (r16 >> 3) + 2 * h;
            int ln  = rr * 4 + q;
            u32 hi, lo; split2(v[i], v[i + 1], hi, lo);
            AF[(((mt * 2 + kt) * 2 + 0) * 32 + ln) * 4 + reg] = hi;
            AF[(((mt * 2 + kt) * 2 + 1) * 32 + ln) * 4 + reg] = lo;
        }
    }
    // ---- wt fragments: mask*nodes in fragment-major float4 ----
    for (int idx = t; idx < 2048; idx += 512) {
        int mt = idx >> 8, nt = (idx >> 5) & 7, ln = idx & 31;
        int rr = ln >> 2, q = ln & 3;
        int mrow = mt * 16 + rr;
        int c = nt * 8 + 2 * q;
        int il = mrow >> 6;
        int jn1 = mrow & 63, jn2 = (mrow + 8) & 63;
        float m1 = mask[(size_t)b * 4096 + (pair * 2 + il) * 64 + jn1];
        float m2 = mask[(size_t)b * 4096 + (pair * 2 + il) * 64 + jn2];
        float2 n1 = *(const float2*)(nodes + ((size_t)b * 64 + jn1) * 64 + c);
        float2 n2 = *(const float2*)(nodes + ((size_t)b * 64 + jn2) * 64 + c);
        float4 w; w.x = n1.x * m1; w.y = n1.y * m1; w.z = n2.x * m2; w.w = n2.y * m2;
        WF4[idx] = w;
    }
    __syncthreads();

    const int q = lane & 3;

    #pragma unroll
    for (int igl = 0; igl < 4; igl++) {
        int ig = wid * 4 + igl;
        float s0 = 0.0f, s1 = 0.0f;

        #pragma unroll
        for (int nh = 0; nh < 4; nh++) {
            // two nt's worth of B fragments (16 regs)
            uint4 Bf[2][2];
            #pragma unroll
            for (int j = 0; j < 2; j++) {
                int nt = nh * 2 + j;
                Bf[j][0] = g_Wfrag4[((ig * 8 + nt) * 2 + 0) * 32 + lane];
                Bf[j][1] = g_Wfrag4[((ig * 8 + nt) * 2 + 1) * 32 + lane];
            }

            #pragma unroll
            for (int mt = 0; mt < 8; mt++) {
                uint4 Ah0 = AF4[((mt * 2 + 0) * 2 + 0) * 32 + lane];
                uint4 Al0 = AF4[((mt * 2 + 0) * 2 + 1) * 32 + lane];
                uint4 Ah1 = AF4[((mt * 2 + 1) * 2 + 0) * 32 + lane];
                uint4 Al1 = AF4[((mt * 2 + 1) * 2 + 1) * 32 + lane];

                float sm_ = 0.0f;
                #pragma unroll
                for (int j = 0; j < 2; j++) {
                    int nt = nh * 2 + j;
                    float2 bb = __ldg((const float2*)(b_e + ig * 64 + nt * 8 + 2 * q));
                    // a-chain: hi*hi (+bias), 2 MMAs
                    float a0 = bb.x, a1 = bb.y, a2 = bb.x, a3 = bb.y;
                    // e-chain: lo*hi + hi*lo, 4 MMAs
                    float e0 = 0, e1 = 0, e2 = 0, e3 = 0;
                    MMA16816(a0,a1,a2,a3, Ah0.x,Ah0.y,Ah0.z,Ah0.w, Bf[j][0].x, Bf[j][0].y);
                    MMA16816(e0,e1,e2,e3, Al0.x,Al0.y,Al0.z,Al0.w, Bf[j][0].x, Bf[j][0].y);
                    MMA16816(a0,a1,a2,a3, Ah1.x,Ah1.y,Ah1.z,Ah1.w, Bf[j][0].z, Bf[j][0].w);
                    MMA16816(e0,e1,e2,e3, Al1.x,Al1.y,Al1.z,Al1.w, Bf[j][0].z, Bf[j][0].w);
                    MMA16816(e0,e1,e2,e3, Ah0.x,Ah0.y,Ah0.z,Ah0.w, Bf[j][1].x, Bf[j][1].y);
                    MMA16816(e0,e1,e2,e3, Ah1.x,Ah1.y,Ah1.z,Ah1.w, Bf[j][1].z, Bf[j][1].w);

                    float4 w = WF4[(mt * 8 + nt) * 32 + lane];
                    sm_ = fmaf(fmaxf(a0 + e0, 0.0f), w.x, sm_);
                    sm_ = fmaf(fmaxf(a1 + e1, 0.0f), w.y, sm_);
                    sm_ = fmaf(fmaxf(a2 + e2, 0.0f), w.z, sm_);
                    sm_ = fmaf(fmaxf(a3 + e3, 0.0f), w.w, sm_);
                }
                if (mt < 4) s0 += sm_; else s1 += sm_;
            }
        }
        // warp reduce; single writer per agg cell -> plain stores
        #pragma unroll
        for (int off = 16; off; off >>= 1) {
            s0 += __shfl_down_sync(0xffffffffu, s0, off);
            s1 += __shfl_down_sync(0xffffffffu, s1, off);
        }
        if (lane == 0) {
            aggs[ig]      = s0;
            aggs[64 + ig] = s1;
        }
    }
    __syncthreads();

    // ---- GRU tail: 2 inodes ----
    for (int il2 = 0; il2 < 2; il2++) {
        __syncthreads();
        if (t < 192) {
            float s = gbias[t];
            #pragma unroll 8
            for (int k = 0; k < 64; k++)
                s = fmaf(xrow[il2 * 64 + k], Kmat[k * 192 + t], s);
            xk1[t] = s;
        }
        __syncthreads();
        if (t < 64) {
            float z  = 1.0f / (1.0f + expf(-(xk1[t] + gbias[192 + t])));
            float r  = 1.0f / (1.0f + expf(-(xk1[64 + t] + gbias[256 + t])));
            float hh = tanhf(xk1[128 + t] + r * gbias[320 + t]);
            h1[t] = (1.0f - z) * hh;   // h was 0
        }
        __syncthreads();
        if (t < 192) {
            float s1g = gbias[t], s2g = gbias[192 + t];
            #pragma unroll 8
            for (int k = 0; k < 64; k++) {
                s1g = fmaf(aggs[il2 * 64 + k], Kmat[k * 192 + t], s1g);
                s2g = fmaf(h1[k],              Rmat[k * 192 + t], s2g);
            }
            xk2[t] = s1g; hk2[t] = s2g;
        }
        __syncthreads();
        if (t < 64) {
            float z  = 1.0f / (1.0f + expf(-(xk2[t] + hk2[t])));
            float r  = 1.0f / (1.0f + expf(-(xk2[64 + t] + hk2[64 + t])));
            float hh = tanhf(xk2[128 + t] + r * hk2[128 + t]);
            out[((size_t)(b * 64 + pair * 2 + il2)) * 64 + t] =
                z * h1[t] + (1.0f - z) * hh;
        }
    }
}

extern "C" void kernel_launch(void* const* d_in, const int* in_sizes, int n_in,
                              void* d_out, int out_size) {
    const float* nodes = (const float*)d_in[0];
    const float* edges = (const float*)d_in[1];
    const float* mask  = (const float*)d_in[2];
    const float* W_e   = (const float*)d_in[3];
    const float* b_e   = (const float*)d_in[4];
    const float* gk    = (const float*)d_in[5];
    const float* gr    = (const float*)d_in[6];
    const float* gb    = (const float*)d_in[7];
    float* out = (float*)d_out;

    conv_w_kernel<<<dim3(16, 4), 256>>>(W_e);

    cudaFuncSetAttribute(mp_mma_kernel,
                         cudaFuncAttributeMaxDynamicSharedMemorySize, SMEM_SZ);
    mp_mma_kernel<<<256, 512, SMEM_SZ>>>(nodes, edges, mask, b_e,
                                         gk, gr, gb, out);
}

// round 10
// speedup vs baseline: 1.1211x; 1.1211x over previous
#include <cuda_runtime.h>
#include <cuda_bf16.h>
#include <math.h>
#include <stdint.h>

// B=8, N=64, D=64, E=32. GEMM view: (32768 x 32) @ (32 x 4096), fused
// relu/mask/reduce epilogue + GRU tail. mma.sync m16n8k16 bf16 (HMMA),
// 3-term hi/lo split. 256 thr x 3 CTAs/SM (85-reg budget, 24 warps/SM):
// R8 was latency-bound at 16 warps; R9's 64-reg bound spilled. This is the
// middle point: B fragments tiled 4-nt (32 regs) to fit the budget.

typedef unsigned int u32;

// W fragment buffer: [ig(64)][nt(8)][term(2)][lane(32)] uint4
__device__ uint4 g_Wfrag4[32768];   // 512 KB

static __device__ __forceinline__ void split2(float v0, float v1, u32& hi, u32& lo) {
    __nv_bfloat16 h0 = __float2bfloat16(v0);
    __nv_bfloat16 h1 = __float2bfloat16(v1);
    __nv_bfloat16 l0 = __float2bfloat16(v0 - __bfloat162float(h0));
    __nv_bfloat16 l1 = __float2bfloat16(v1 - __bfloat162float(h1));
    hi = ((u32)__bfloat16_as_ushort(h1) << 16) | (u32)__bfloat16_as_ushort(h0);
    lo = ((u32)__bfloat16_as_ushort(l1) << 16) | (u32)__bfloat16_as_ushort(l0);
}

#define MMA16816(c0,c1,c2,c3,a0,a1,a2,a3,b0,b1) \
    asm volatile("mma.sync.aligned.m16n8k16.row.col.f32.bf16.bf16.f32 " \
        "{%0,%1,%2,%3},{%4,%5,%6,%7},{%8,%9},{%0,%1,%2,%3};" \
        : "+f"(c0),"+f"(c1),"+f"(c2),"+f"(c3) \
        : "r"(a0),"r"(a1),"r"(a2),"r"(a3),"r"(b0),"r"(b1))

// ---------------- converter: W_e -> bf16 hi/lo fragments ----------------
__global__ void conv_w_kernel(const float* __restrict__ W_e) {
    int qg = blockIdx.x;                 // k-pair 0..15
    int kt = qg >> 3, h = (qg >> 2) & 1, q = qg & 3;
    int k0 = qg * 2;
    u32* W = (u32*)g_Wfrag4;
    int col = blockIdx.y * 1024 + threadIdx.x;
    #pragma unroll
    for (int u = 0; u < 4; u++, col += 256) {
        float w0 = W_e[(size_t)k0 * 4096 + col];
        float w1 = W_e[(size_t)(k0 + 1) * 4096 + col];
        u32 hi, lo; split2(w0, w1, hi, lo);
        int ig = col >> 6, nt = (col >> 3) & 7, n = col & 7;
        int base = ((((ig * 8 + nt) * 2 + 0) * 8 + n) * 4 + q) * 4 + kt * 2 + h;
        W[base]       = hi;
        W[base + 128] = lo;
    }
}

// ---------------- main kernel ----------------
// dynamic smem layout (bytes)
#define OFF_AF    0        // A frags: [mt(8)][kt(2)][term(2)][lane(32)] uint4 = 16KB
#define OFF_WF    16384    // wt frags: [mt(8)][nt(8)][lane(32)] float4 = 32KB
#define OFF_AGGS  49152    // 128 f
#define OFF_XROW  49664    // 128 f
#define OFF_XK1   50176    // 192 f
#define OFF_H1    50944    // 64 f
#define OFF_XK2   51200    // 192 f
#define OFF_HK2   51968    // 192 f
#define SMEM_SZ   52736

__global__ __launch_bounds__(256, 3) void mp_mma_kernel(
    const float* __restrict__ nodes,   // (8,64,64)
    const float* __restrict__ edges,   // (8,4096,32)
    const float* __restrict__ mask,    // (8,4096,1)
    const float* __restrict__ b_e,     // (4096,)
    const float* __restrict__ Kmat,    // (64,192)
    const float* __restrict__ Rmat,    // (64,192)
    const float* __restrict__ gbias,   // (2,192)
    float* __restrict__ out)           // (8,64,64)
{
    extern __shared__ char sm[];
    u32*    AF   = (u32*)(sm + OFF_AF);
    uint4*  AF4  = (uint4*)(sm + OFF_AF);
    float4* WF4  = (float4*)(sm + OFF_WF);
    float*  aggs = (float*)(sm + OFF_AGGS);
    float*  xrow = (float*)(sm + OFF_XROW);
    float*  xk1  = (float*)(sm + OFF_XK1);
    float*  h1   = (float*)(sm + OFF_H1);
    float*  xk2  = (float*)(sm + OFF_XK2);
    float*  hk2  = (float*)(sm + OFF_HK2);

    const int t    = threadIdx.x;
    const int lane = t & 31;
    const int wid  = t >> 5;          // 0..7
    const int b    = blockIdx.x >> 5;
    const int pair = blockIdx.x & 31;

    if (t < 128)
        xrow[t] = nodes[((size_t)b * 64 + pair * 2 + (t >> 6)) * 64 + (t & 63)];

    // ---- A conversion: edges rows -> fragment-major hi/lo in smem ----
    {
        int m = t >> 1, half = t & 1;
        int mt = m >> 4, r16 = m & 15, rr = r16 & 7;
        const float* ar = edges + ((size_t)(b * 4096 + pair * 128 + m)) * 32 + half * 16;
        float v[16];
        #pragma unroll
        for (int i = 0; i < 16; i += 4) {
            float4 x = *(const float4*)(ar + i);
            v[i] = x.x; v[i + 1] = x.y; v[i + 2] = x.z; v[i + 3] = x.w;
        }
        #pragma unroll
        for (int i = 0; i < 16; i += 2) {
            int qg = half * 8 + (i >> 1);          // global k-pair 0..15
            int kt = qg >> 3, ql = qg & 7;
            int q = ql & 3, h = ql >> 2;
            int reg = (r16 >> 3) + 2 * h;
            int ln  = rr * 4 + q;
            u32 hi, lo; split2(v[i], v[i + 1], hi, lo);
            AF[(((mt * 2 + kt) * 2 + 0) * 32 + ln) * 4 + reg] = hi;
            AF[(((mt * 2 + kt) * 2 + 1) * 32 + ln) * 4 + reg] = lo;
        }
    }
    // ---- wt fragments: mask*nodes in fragment-major float4 ----
    for (int idx = t; idx < 2048; idx += 256) {
        int mt = idx >> 8, nt = (idx >> 5) & 7, ln = idx & 31;
        int rr = ln >> 2, q = ln & 3;
        int mrow = mt * 16 + rr;
        int c = nt * 8 + 2 * q;
        int il = mrow >> 6;
        int jn1 = mrow & 63, jn2 = (mrow + 8) & 63;
        float m1 = mask[(size_t)b * 4096 + (pair * 2 + il) * 64 + jn1];
        float m2 = mask[(size_t)b * 4096 + (pair * 2 + il) * 64 + jn2];
        float2 n1 = *(const float2*)(nodes + ((size_t)b * 64 + jn1) * 64 + c);
        float2 n2 = *(const float2*)(nodes + ((size_t)b * 64 + jn2) * 64 + c);
        float4 w; w.x = n1.x * m1; w.y = n1.y * m1; w.z = n2.x * m2; w.w = n2.y * m2;
        WF4[idx] = w;
    }
    __syncthreads();

    const int q = lane & 3;

    for (int igl = 0; igl < 8; igl++) {
        int ig = wid * 8 + igl;
        float s0 = 0.0f, s1 = 0.0f;

        #pragma unroll
        for (int nh = 0; nh < 2; nh++) {
            // four nt's worth of B fragments (32 regs)
            uint4 Bf[4][2];
            #pragma unroll
            for (int j = 0; j < 4; j++) {
                int nt = nh * 4 + j;
                Bf[j][0] = g_Wfrag4[((ig * 8 + nt) * 2 + 0) * 32 + lane];
                Bf[j][1] = g_Wfrag4[((ig * 8 + nt) * 2 + 1) * 32 + lane];
            }

            #pragma unroll
            for (int mt = 0; mt < 8; mt++) {
                uint4 Ah0 = AF4[((mt * 2 + 0) * 2 + 0) * 32 + lane];
                uint4 Al0 = AF4[((mt * 2 + 0) * 2 + 1) * 32 + lane];
                uint4 Ah1 = AF4[((mt * 2 + 1) * 2 + 0) * 32 + lane];
                uint4 Al1 = AF4[((mt * 2 + 1) * 2 + 1) * 32 + lane];

                float sm_ = 0.0f;
                #pragma unroll
                for (int j = 0; j < 4; j++) {
                    int nt = nh * 4 + j;
                    float2 bb = __ldg((const float2*)(b_e + ig * 64 + nt * 8 + 2 * q));
                    // a-chain: hi*hi (+bias); e-chain: lo*hi + hi*lo
                    float a0 = bb.x, a1 = bb.y, a2 = bb.x, a3 = bb.y;
                    float e0 = 0, e1 = 0, e2 = 0, e3 = 0;
                    MMA16816(a0,a1,a2,a3, Ah0.x,Ah0.y,Ah0.z,Ah0.w, Bf[j][0].x, Bf[j][0].y);
                    MMA16816(e0,e1,e2,e3, Al0.x,Al0.y,Al0.z,Al0.w, Bf[j][0].x, Bf[j][0].y);
                    MMA16816(a0,a1,a2,a3, Ah1.x,Ah1.y,Ah1.z,Ah1.w, Bf[j][0].z, Bf[j][0].w);
                    MMA16816(e0,e1,e2,e3, Al1.x,Al1.y,Al1.z,Al1.w, Bf[j][0].z, Bf[j][0].w);
                    MMA16816(e0,e1,e2,e3, Ah0.x,Ah0.y,Ah0.z,Ah0.w, Bf[j][1].x, Bf[j][1].y);
                    MMA16816(e0,e1,e2,e3, Ah1.x,Ah1.y,Ah1.z,Ah1.w, Bf[j][1].z, Bf[j][1].w);

                    float4 w = WF4[(mt * 8 + nt) * 32 + lane];
                    sm_ = fmaf(fmaxf(a0 + e0, 0.0f), w.x, sm_);
                    sm_ = fmaf(fmaxf(a1 + e1, 0.0f), w.y, sm_);
                    sm_ = fmaf(fmaxf(a2 + e2, 0.0f), w.z, sm_);
                    sm_ = fmaf(fmaxf(a3 + e3, 0.0f), w.w, sm_);
                }
                if (mt < 4) s0 += sm_; else s1 += sm_;
            }
        }
        // warp reduce; single writer per agg cell -> plain stores
        #pragma unroll
        for (int off = 16; off; off >>= 1) {
            s0 += __shfl_down_sync(0xffffffffu, s0, off);
            s1 += __shfl_down_sync(0xffffffffu, s1, off);
        }
        if (lane == 0) {
            aggs[ig]      = s0;
            aggs[64 + ig] = s1;
        }
    }
    __syncthreads();

    // ---- GRU tail: 2 inodes ----
    for (int il2 = 0; il2 < 2; il2++) {
        __syncthreads();
        if (t < 192) {
            float s = gbias[t];
            #pragma unroll 8
            for (int k = 0; k < 64; k++)
                s = fmaf(xrow[il2 * 64 + k], Kmat[k * 192 + t], s);
            xk1[t] = s;
        }
        __syncthreads();
        if (t < 64) {
            float z  = 1.0f / (1.0f + expf(-(xk1[t] + gbias[192 + t])));
            float r  = 1.0f / (1.0f + expf(-(xk1[64 + t] + gbias[256 + t])));
            float hh = tanhf(xk1[128 + t] + r * gbias[320 + t]);
            h1[t] = (1.0f - z) * hh;   // h was 0
        }
        __syncthreads();
        if (t < 192) {
            float s1g = gbias[t], s2g = gbias[192 + t];
            #pragma unroll 8
            for (int k = 0; k < 64; k++) {
                s1g = fmaf(aggs[il2 * 64 + k], Kmat[k * 192 + t], s1g);
                s2g = fmaf(h1[k],              Rmat[k * 192 + t], s2g);
            }
            xk2[t] = s1g; hk2[t] = s2g;
        }
        __syncthreads();
        if (t < 64) {
            float z  = 1.0f / (1.0f + expf(-(xk2[t] + hk2[t])));
            float r  = 1.0f / (1.0f + expf(-(xk2[64 + t] + hk2[64 + t])));
            float hh = tanhf(xk2[128 + t] + r * hk2[128 + t]);
            out[((size_t)(b * 64 + pair * 2 + il2)) * 64 + t] =
                z * h1[t] + (1.0f - z) * hh;
        }
    }
}

extern "C" void kernel_launch(void* const* d_in, const int* in_sizes, int n_in,
                              void* d_out, int out_size) {
    const float* nodes = (const float*)d_in[0];
    const float* edges = (const float*)d_in[1];
    const float* mask  = (const float*)d_in[2];
    const float* W_e   = (const float*)d_in[3];
    const float* b_e   = (const float*)d_in[4];
    const float* gk    = (const float*)d_in[5];
    const float* gr    = (const float*)d_in[6];
    const float* gb    = (const float*)d_in[7];
    float* out = (float*)d_out;

    conv_w_kernel<<<dim3(16, 4), 256>>>(W_e);

    cudaFuncSetAttribute(mp_mma_kernel,
                         cudaFuncAttributeMaxDynamicSharedMemorySize, SMEM_SZ);
    mp_mma_kernel<<<256, 256, SMEM_SZ>>>(nodes, edges, mask, b_e,
                                         gk, gr, gb, out);
}

// round 11
// speedup vs baseline: 2.7168x; 2.4232x over previous
#include <cuda_runtime.h>
#include <cuda_bf16.h>
#include <math.h>
#include <stdint.h>

// B=8, N=64, D=64, E=32. GEMM view: (32768 x 32) @ (32 x 4096), fused
// relu/mask/reduce epilogue + GRU tail. mma.sync m16n8k16 bf16 (HMMA),
// 3-term hi/lo split. 256 thr, 2 CTAs/SM, 128-reg budget (no spill).
// Each warp processes TWO i-groups concurrently -> 4 independent MMA
// chains in flight (latency cover without occupancy, which spills).

typedef unsigned int u32;

// W fragment buffer: [ig(64)][nt(8)][term(2)][lane(32)] uint4
__device__ uint4 g_Wfrag4[32768];   // 512 KB

static __device__ __forceinline__ void split2(float v0, float v1, u32& hi, u32& lo) {
    __nv_bfloat16 h0 = __float2bfloat16(v0);
    __nv_bfloat16 h1 = __float2bfloat16(v1);
    __nv_bfloat16 l0 = __float2bfloat16(v0 - __bfloat162float(h0));
    __nv_bfloat16 l1 = __float2bfloat16(v1 - __bfloat162float(h1));
    hi = ((u32)__bfloat16_as_ushort(h1) << 16) | (u32)__bfloat16_as_ushort(h0);
    lo = ((u32)__bfloat16_as_ushort(l1) << 16) | (u32)__bfloat16_as_ushort(l0);
}

#define MMA16816(c0,c1,c2,c3,a0,a1,a2,a3,b0,b1) \
    asm volatile("mma.sync.aligned.m16n8k16.row.col.f32.bf16.bf16.f32 " \
        "{%0,%1,%2,%3},{%4,%5,%6,%7},{%8,%9},{%0,%1,%2,%3};" \
        : "+f"(c0),"+f"(c1),"+f"(c2),"+f"(c3) \
        : "r"(a0),"r"(a1),"r"(a2),"r"(a3),"r"(b0),"r"(b1))

// ---------------- converter: W_e -> bf16 hi/lo fragments ----------------
__global__ void conv_w_kernel(const float* __restrict__ W_e) {
    int qg = blockIdx.x;                 // k-pair 0..15
    int kt = qg >> 3, h = (qg >> 2) & 1, q = qg & 3;
    int k0 = qg * 2;
    u32* W = (u32*)g_Wfrag4;
    int col = blockIdx.y * 1024 + threadIdx.x;
    #pragma unroll
    for (int u = 0; u < 4; u++, col += 256) {
        float w0 = W_e[(size_t)k0 * 4096 + col];
        float w1 = W_e[(size_t)(k0 + 1) * 4096 + col];
        u32 hi, lo; split2(w0, w1, hi, lo);
        int ig = col >> 6, nt = (col >> 3) & 7, n = col & 7;
        int base = ((((ig * 8 + nt) * 2 + 0) * 8 + n) * 4 + q) * 4 + kt * 2 + h;
        W[base]       = hi;
        W[base + 128] = lo;
    }
}

// ---------------- main kernel ----------------
// dynamic smem layout (bytes)
#define OFF_AF    0        // A frags: [mt(8)][kt(2)][term(2)][lane(32)] uint4 = 16KB
#define OFF_WF    16384    // wt frags: [mt(8)][nt(8)][lane(32)] float4 = 32KB
#define OFF_AGGS  49152    // 128 f
#define OFF_XROW  49664    // 128 f
#define OFF_XK1   50176    // 192 f
#define OFF_H1    50944    // 64 f
#define OFF_XK2   51200    // 192 f
#define OFF_HK2   51968    // 192 f
#define SMEM_SZ   52736

__global__ __launch_bounds__(256, 2) void mp_mma_kernel(
    const float* __restrict__ nodes,   // (8,64,64)
    const float* __restrict__ edges,   // (8,4096,32)
    const float* __restrict__ mask,    // (8,4096,1)
    const float* __restrict__ b_e,     // (4096,)
    const float* __restrict__ Kmat,    // (64,192)
    const float* __restrict__ Rmat,    // (64,192)
    const float* __restrict__ gbias,   // (2,192)
    float* __restrict__ out)           // (8,64,64)
{
    extern __shared__ char sm[];
    u32*    AF   = (u32*)(sm + OFF_AF);
    uint4*  AF4  = (uint4*)(sm + OFF_AF);
    float4* WF4  = (float4*)(sm + OFF_WF);
    float*  aggs = (float*)(sm + OFF_AGGS);
    float*  xrow = (float*)(sm + OFF_XROW);
    float*  xk1  = (float*)(sm + OFF_XK1);
    float*  h1   = (float*)(sm + OFF_H1);
    float*  xk2  = (float*)(sm + OFF_XK2);
    float*  hk2  = (float*)(sm + OFF_HK2);

    const int t    = threadIdx.x;
    const int lane = t & 31;
    const int wid  = t >> 5;          // 0..7
    const int b    = blockIdx.x >> 5;
    const int pair = blockIdx.x & 31;

    if (t < 128)
        xrow[t] = nodes[((size_t)b * 64 + pair * 2 + (t >> 6)) * 64 + (t & 63)];

    // ---- A conversion: edges rows -> fragment-major hi/lo in smem ----
    {
        int m = t >> 1, half = t & 1;
        int mt = m >> 4, r16 = m & 15, rr = r16 & 7;
        const float* ar = edges + ((size_t)(b * 4096 + pair * 128 + m)) * 32 + half * 16;
        float v[16];
        #pragma unroll
        for (int i = 0; i < 16; i += 4) {
            float4 x = *(const float4*)(ar + i);
            v[i] = x.x; v[i + 1] = x.y; v[i + 2] = x.z; v[i + 3] = x.w;
        }
        #pragma unroll
        for (int i = 0; i < 16; i += 2) {
            int qg = half * 8 + (i >> 1);          // global k-pair 0..15
            int kt = qg >> 3, ql = qg & 7;
            int q = ql & 3, h = ql >> 2;
            int reg = (r16 >> 3) + 2 * h;
            int ln  = rr * 4 + q;
            u32 hi, lo; split2(v[i], v[i + 1], hi, lo);
            AF[(((mt * 2 + kt) * 2 + 0) * 32 + ln) * 4 + reg] = hi;
            AF[(((mt * 2 + kt) * 2 + 1) * 32 + ln) * 4 + reg] = lo;
        }
    }
    // ---- wt fragments: mask*nodes in fragment-major float4 ----
    for (int idx = t; idx < 2048; idx += 256) {
        int mt = idx >> 8, nt = (idx >> 5) & 7, ln = idx & 31;
        int rr = ln >> 2, q = ln & 3;
        int mrow = mt * 16 + rr;
        int c = nt * 8 + 2 * q;
        int il = mrow >> 6;
        int jn1 = mrow & 63, jn2 = (mrow + 8) & 63;
        float m1 = mask[(size_t)b * 4096 + (pair * 2 + il) * 64 + jn1];
        float m2 = mask[(size_t)b * 4096 + (pair * 2 + il) * 64 + jn2];
        float2 n1 = *(const float2*)(nodes + ((size_t)b * 64 + jn1) * 64 + c);
        float2 n2 = *(const float2*)(nodes + ((size_t)b * 64 + jn2) * 64 + c);
        float4 w; w.x = n1.x * m1; w.y = n1.y * m1; w.z = n2.x * m2; w.w = n2.y * m2;
        WF4[idx] = w;
    }
    __syncthreads();

    const int q = lane & 3;

    for (int igp = 0; igp < 4; igp++) {
        const int ig0 = wid * 8 + igp * 2;
        const int ig1 = ig0 + 1;
        float s00 = 0.f, s01 = 0.f, s10 = 0.f, s11 = 0.f;  // [ig][mhalf]

        #pragma unroll
        for (int nh = 0; nh < 4; nh++) {
            // B frags: [ig(2)][nt-in-pair(2)][term(2)] = 8 uint4
            uint4 B0[2][2], B1[2][2];
            #pragma unroll
            for (int j = 0; j < 2; j++) {
                int nt = nh * 2 + j;
                B0[j][0] = g_Wfrag4[((ig0 * 8 + nt) * 2 + 0) * 32 + lane];
                B0[j][1] = g_Wfrag4[((ig0 * 8 + nt) * 2 + 1) * 32 + lane];
                B1[j][0] = g_Wfrag4[((ig1 * 8 + nt) * 2 + 0) * 32 + lane];
                B1[j][1] = g_Wfrag4[((ig1 * 8 + nt) * 2 + 1) * 32 + lane];
            }
            // bias, hoisted out of the mt loop: [ig][j]
            float2 bb0[2], bb1[2];
            #pragma unroll
            for (int j = 0; j < 2; j++) {
                int nt = nh * 2 + j;
                bb0[j] = __ldg((const float2*)(b_e + ig0 * 64 + nt * 8 + 2 * q));
                bb1[j] = __ldg((const float2*)(b_e + ig1 * 64 + nt * 8 + 2 * q));
            }

            #pragma unroll
            for (int mt = 0; mt < 8; mt++) {
                uint4 Ah0 = AF4[((mt * 2 + 0) * 2 + 0) * 32 + lane];
                uint4 Al0 = AF4[((mt * 2 + 0) * 2 + 1) * 32 + lane];
                uint4 Ah1 = AF4[((mt * 2 + 1) * 2 + 0) * 32 + lane];
                uint4 Al1 = AF4[((mt * 2 + 1) * 2 + 1) * 32 + lane];

                float sm0 = 0.f, sm1 = 0.f;
                #pragma unroll
                for (int j = 0; j < 2; j++) {
                    int nt = nh * 2 + j;
                    // ig0: a-chain (hi*hi + bias), e-chain (lo*hi + hi*lo)
                    float a0 = bb0[j].x, a1 = bb0[j].y, a2 = bb0[j].x, a3 = bb0[j].y;
                    float e0 = 0, e1 = 0, e2 = 0, e3 = 0;
                    // ig1: same
                    float f0 = bb1[j].x, f1 = bb1[j].y, f2 = bb1[j].x, f3 = bb1[j].y;
                    float g0 = 0, g1 = 0, g2 = 0, g3 = 0;

                    MMA16816(a0,a1,a2,a3, Ah0.x,Ah0.y,Ah0.z,Ah0.w, B0[j][0].x, B0[j][0].y);
                    MMA16816(f0,f1,f2,f3, Ah0.x,Ah0.y,Ah0.z,Ah0.w, B1[j][0].x, B1[j][0].y);
                    MMA16816(e0,e1,e2,e3, Al0.x,Al0.y,Al0.z,Al0.w, B0[j][0].x, B0[j][0].y);
                    MMA16816(g0,g1,g2,g3, Al0.x,Al0.y,Al0.z,Al0.w, B1[j][0].x, B1[j][0].y);
                    MMA16816(a0,a1,a2,a3, Ah1.x,Ah1.y,Ah1.z,Ah1.w, B0[j][0].z, B0[j][0].w);
                    MMA16816(f0,f1,f2,f3, Ah1.x,Ah1.y,Ah1.z,Ah1.w, B1[j][0].z, B1[j][0].w);
                    MMA16816(e0,e1,e2,e3, Al1.x,Al1.y,Al1.z,Al1.w, B0[j][0].z, B0[j][0].w);
                    MMA16816(g0,g1,g2,g3, Al1.x,Al1.y,Al1.z,Al1.w, B1[j][0].z, B1[j][0].w);
                    MMA16816(e0,e1,e2,e3, Ah0.x,Ah0.y,Ah0.z,Ah0.w, B0[j][1].x, B0[j][1].y);
                    MMA16816(g0,g1,g2,g3, Ah0.x,Ah0.y,Ah0.z,Ah0.w, B1[j][1].x, B1[j][1].y);
                    MMA16816(e0,e1,e2,e3, Ah1.x,Ah1.y,Ah1.z,Ah1.w, B0[j][1].z, B0[j][1].w);
                    MMA16816(g0,g1,g2,g3, Ah1.x,Ah1.y,Ah1.z,Ah1.w, B1[j][1].z, B1[j][1].w);

                    float4 w = WF4[(mt * 8 + nt) * 32 + lane];
                    sm0 = fmaf(fmaxf(a0 + e0, 0.0f), w.x, sm0);
                    sm0 = fmaf(fmaxf(a1 + e1, 0.0f), w.y, sm0);
                    sm0 = fmaf(fmaxf(a2 + e2, 0.0f), w.z, sm0);
                    sm0 = fmaf(fmaxf(a3 + e3, 0.0f), w.w, sm0);
                    sm1 = fmaf(fmaxf(f0 + g0, 0.0f), w.x, sm1);
                    sm1 = fmaf(fmaxf(f1 + g1, 0.0f), w.y, sm1);
                    sm1 = fmaf(fmaxf(f2 + g2, 0.0f), w.z, sm1);
                    sm1 = fmaf(fmaxf(f3 + g3, 0.0f), w.w, sm1);
                }
                if (mt < 4) { s00 += sm0; s10 += sm1; }
                else        { s01 += sm0; s11 += sm1; }
            }
        }
        // warp reduce; single writer per agg cell -> plain stores
        #pragma unroll
        for (int off = 16; off; off >>= 1) {
            s00 += __shfl_down_sync(0xffffffffu, s00, off);
            s01 += __shfl_down_sync(0xffffffffu, s01, off);
            s10 += __shfl_down_sync(0xffffffffu, s10, off);
            s11 += __shfl_down_sync(0xffffffffu, s11, off);
        }
        if (lane == 0) {
            aggs[ig0]      = s00;
            aggs[64 + ig0] = s01;
            aggs[ig1]      = s10;
            aggs[64 + ig1] = s11;
        }
    }
    __syncthreads();

    // ---- GRU tail: 2 inodes ----
    for (int il2 = 0; il2 < 2; il2++) {
        __syncthreads();
        if (t < 192) {
            float s = gbias[t];
            #pragma unroll 8
            for (int k = 0; k < 64; k++)
                s = fmaf(xrow[il2 * 64 + k], Kmat[k * 192 + t], s);
            xk1[t] = s;
        }
        __syncthreads();
        if (t < 64) {
            float z  = 1.0f / (1.0f + expf(-(xk1[t] + gbias[192 + t])));
            float r  = 1.0f / (1.0f + expf(-(xk1[64 + t] + gbias[256 + t])));
            float hh = tanhf(xk1[128 + t] + r * gbias[320 + t]);
            h1[t] = (1.0f - z) * hh;   // h was 0
        }
        __syncthreads();
        if (t < 192) {
            float s1g = gbias[t], s2g = gbias[192 + t];
            #pragma unroll 8
            for (int k = 0; k < 64; k++) {
                s1g = fmaf(aggs[il2 * 64 + k], Kmat[k * 192 + t], s1g);
                s2g = fmaf(h1[k],              Rmat[k * 192 + t], s2g);
            }
            xk2[t] = s1g; hk2[t] = s2g;
        }
        __syncthreads();
        if (t < 64) {
            float z  = 1.0f / (1.0f + expf(-(xk2[t] + hk2[t])));
            float r  = 1.0f / (1.0f + expf(-(xk2[64 + t] + hk2[64 + t])));
            float hh = tanhf(xk2[128 + t] + r * hk2[128 + t]);
            out[((size_t)(b * 64 + pair * 2 + il2)) * 64 + t] =
                z * h1[t] + (1.0f - z) * hh;
        }
    }
}

extern "C" void kernel_launch(void* const* d_in, const int* in_sizes, int n_in,
                              void* d_out, int out_size) {
    const float* nodes = (const float*)d_in[0];
    const float* edges = (const float*)d_in[1];
    const float* mask  = (const float*)d_in[2];
    const float* W_e   = (const float*)d_in[3];
    const float* b_e   = (const float*)d_in[4];
    const float* gk    = (const float*)d_in[5];
    const float* gr    = (const float*)d_in[6];
    const float* gb    = (const float*)d_in[7];
    float* out = (float*)d_out;

    conv_w_kernel<<<dim3(16, 4), 256>>>(W_e);

    cudaFuncSetAttribute(mp_mma_kernel,
                         cudaFuncAttributeMaxDynamicSharedMemorySize, SMEM_SZ);
    mp_mma_kernel<<<256, 256, SMEM_SZ>>>(nodes, edges, mask, b_e,
                                         gk, gr, gb, out);
}

// round 13
// speedup vs baseline: 2.8953x; 1.0657x over previous
#include <cuda_runtime.h>
#include <cuda_bf16.h>
#include <math.h>
#include <stdint.h>

// B=8, N=64, D=64, E=32. GEMM view: (32768 x 32) @ (32 x 4096), fused
// relu/mask/reduce epilogue + GRU tail. mma.sync m16n8k16 bf16 (HMMA),
// 3-term hi/lo split. 256 thr, 2 CTAs/SM. Two i-groups per warp iter
// -> 4 independent MMA chains (latency cover), with nt-singles to keep
// the live register set small enough to avoid the R9/R10/R11 spills.

typedef unsigned int u32;

// W fragment buffer: [ig(64)][nt(8)][term(2)][lane(32)] uint4
__device__ uint4 g_Wfrag4[32768];   // 512 KB

static __device__ __forceinline__ void split2(float v0, float v1, u32& hi, u32& lo) {
    __nv_bfloat16 h0 = __float2bfloat16(v0);
    __nv_bfloat16 h1 = __float2bfloat16(v1);
    __nv_bfloat16 l0 = __float2bfloat16(v0 - __bfloat162float(h0));
    __nv_bfloat16 l1 = __float2bfloat16(v1 - __bfloat162float(h1));
    hi = ((u32)__bfloat16_as_ushort(h1) << 16) | (u32)__bfloat16_as_ushort(h0);
    lo = ((u32)__bfloat16_as_ushort(l1) << 16) | (u32)__bfloat16_as_ushort(l0);
}

#define MMA16816(c0,c1,c2,c3,a0,a1,a2,a3,b0,b1) \
    asm volatile("mma.sync.aligned.m16n8k16.row.col.f32.bf16.bf16.f32 " \
        "{%0,%1,%2,%3},{%4,%5,%6,%7},{%8,%9},{%0,%1,%2,%3};" \
        : "+f"(c0),"+f"(c1),"+f"(c2),"+f"(c3) \
        : "r"(a0),"r"(a1),"r"(a2),"r"(a3),"r"(b0),"r"(b1))

// ---------------- converter: W_e -> bf16 hi/lo fragments ----------------
__global__ void conv_w_kernel(const float* __restrict__ W_e) {
    int qg = blockIdx.x;                 // k-pair 0..15
    int kt = qg >> 3, h = (qg >> 2) & 1, q = qg & 3;
    int k0 = qg * 2;
    u32* W = (u32*)g_Wfrag4;
    int col = blockIdx.y * 1024 + threadIdx.x;
    #pragma unroll
    for (int u = 0; u < 4; u++, col += 256) {
        float w0 = W_e[(size_t)k0 * 4096 + col];
        float w1 = W_e[(size_t)(k0 + 1) * 4096 + col];
        u32 hi, lo; split2(w0, w1, hi, lo);
        int ig = col >> 6, nt = (col >> 3) & 7, n = col & 7;
        int base = ((((ig * 8 + nt) * 2 + 0) * 8 + n) * 4 + q) * 4 + kt * 2 + h;
        W[base]       = hi;
        W[base + 128] = lo;
    }
}

// ---------------- main kernel ----------------
// dynamic smem layout (bytes)
#define OFF_AF    0        // A frags: [mt(8)][kt(2)][term(2)][lane(32)] uint4 = 16KB
#define OFF_WF    16384    // wt frags: [mt(8)][nt(8)][lane(32)] float4 = 32KB
#define OFF_AGGS  49152    // 128 f
#define OFF_XROW  49664    // 128 f
#define OFF_XK1   50176    // 192 f
#define OFF_H1    50944    // 64 f
#define OFF_XK2   51200    // 192 f
#define OFF_HK2   51968    // 192 f
#define SMEM_SZ   52736

__global__ __launch_bounds__(256, 2) void mp_mma_kernel(
    const float* __restrict__ nodes,   // (8,64,64)
    const float* __restrict__ edges,   // (8,4096,32)
    const float* __restrict__ mask,    // (8,4096,1)
    const float* __restrict__ b_e,     // (4096,)
    const float* __restrict__ Kmat,    // (64,192)
    const float* __restrict__ Rmat,    // (64,192)
    const float* __restrict__ gbias,   // (2,192)
    float* __restrict__ out)           // (8,64,64)
{
    extern __shared__ char sm[];
    u32*    AF   = (u32*)(sm + OFF_AF);
    uint4*  AF4  = (uint4*)(sm + OFF_AF);
    float4* WF4  = (float4*)(sm + OFF_WF);
    float*  aggs = (float*)(sm + OFF_AGGS);
    float*  xrow = (float*)(sm + OFF_XROW);
    float*  xk1  = (float*)(sm + OFF_XK1);
    float*  h1   = (float*)(sm + OFF_H1);
    float*  xk2  = (float*)(sm + OFF_XK2);
    float*  hk2  = (float*)(sm + OFF_HK2);

    const int t    = threadIdx.x;
    const int lane = t & 31;
    const int wid  = t >> 5;          // 0..7
    const int b    = blockIdx.x >> 5;
    const int pair = blockIdx.x & 31;

    if (t < 128)
        xrow[t] = nodes[((size_t)b * 64 + pair * 2 + (t >> 6)) * 64 + (t & 63)];

    // ---- A conversion: edges rows -> fragment-major hi/lo in smem ----
    {
        int m = t >> 1, half = t & 1;
        int mt = m >> 4, r16 = m & 15, rr = r16 & 7;
        const float* ar = edges + ((size_t)(b * 4096 + pair * 128 + m)) * 32 + half * 16;
        float v[16];
        #pragma unroll
        for (int i = 0; i < 16; i += 4) {
            float4 x = *(const float4*)(ar + i);
            v[i] = x.x; v[i + 1] = x.y; v[i + 2] = x.z; v[i + 3] = x.w;
        }
        #pragma unroll
        for (int i = 0; i < 16; i += 2) {
            int qg = half * 8 + (i >> 1);          // global k-pair 0..15
            int kt = qg >> 3, ql = qg & 7;
            int q = ql & 3, h = ql >> 2;
            int reg = (r16 >> 3) + 2 * h;
            int ln  = rr * 4 + q;
            u32 hi, lo; split2(v[i], v[i + 1], hi, lo);
            AF[(((mt * 2 + kt) * 2 + 0) * 32 + ln) * 4 + reg] = hi;
            AF[(((mt * 2 + kt) * 2 + 1) * 32 + ln) * 4 + reg] = lo;
        }
    }
    // ---- wt fragments: mask*nodes in fragment-major float4 ----
    for (int idx = t; idx < 2048; idx += 256) {
        int mt = idx >> 8, nt = (idx >> 5) & 7, ln = idx & 31;
        int rr = ln >> 2, q = ln & 3;
        int mrow = mt * 16 + rr;
        int c = nt * 8 + 2 * q;
        int il = mrow >> 6;
        int jn1 = mrow & 63, jn2 = (mrow + 8) & 63;
        float m1 = mask[(size_t)b * 4096 + (pair * 2 + il) * 64 + jn1];
        float m2 = mask[(size_t)b * 4096 + (pair * 2 + il) * 64 + jn2];
        float2 n1 = *(const float2*)(nodes + ((size_t)b * 64 + jn1) * 64 + c);
        float2 n2 = *(const float2*)(nodes + ((size_t)b * 64 + jn2) * 64 + c);
        float4 w; w.x = n1.x * m1; w.y = n1.y * m1; w.z = n2.x * m2; w.w = n2.y * m2;
        WF4[idx] = w;
    }
    __syncthreads();

    const int q = lane & 3;

    for (int igp = 0; igp < 4; igp++) {
        const int ig0 = wid * 8 + igp * 2;
        const int ig1 = ig0 + 1;
        float s00 = 0.f, s01 = 0.f, s10 = 0.f, s11 = 0.f;  // [ig][mhalf]

        #pragma unroll
        for (int nt = 0; nt < 8; nt++) {
            // B frags for one nt, both igs: 4 uint4 = 16 regs
            uint4 B0h = g_Wfrag4[((ig0 * 8 + nt) * 2 + 0) * 32 + lane];
            uint4 B0l = g_Wfrag4[((ig0 * 8 + nt) * 2 + 1) * 32 + lane];
            uint4 B1h = g_Wfrag4[((ig1 * 8 + nt) * 2 + 0) * 32 + lane];
            uint4 B1l = g_Wfrag4[((ig1 * 8 + nt) * 2 + 1) * 32 + lane];
            float2 bb0 = __ldg((const float2*)(b_e + ig0 * 64 + nt * 8 + 2 * q));
            float2 bb1 = __ldg((const float2*)(b_e + ig1 * 64 + nt * 8 + 2 * q));

            #pragma unroll
            for (int mt = 0; mt < 8; mt++) {
                uint4 Ah0 = AF4[((mt * 2 + 0) * 2 + 0) * 32 + lane];
                uint4 Al0 = AF4[((mt * 2 + 0) * 2 + 1) * 32 + lane];
                uint4 Ah1 = AF4[((mt * 2 + 1) * 2 + 0) * 32 + lane];
                uint4 Al1 = AF4[((mt * 2 + 1) * 2 + 1) * 32 + lane];

                // 4 independent chains: a (hi*hi + bias) and e (cross) per ig
                float a0 = bb0.x, a1 = bb0.y, a2 = bb0.x, a3 = bb0.y;
                float e0 = 0, e1 = 0, e2 = 0, e3 = 0;
                float f0 = bb1.x, f1 = bb1.y, f2 = bb1.x, f3 = bb1.y;
                float g0 = 0, g1 = 0, g2 = 0, g3 = 0;

                MMA16816(a0,a1,a2,a3, Ah0.x,Ah0.y,Ah0.z,Ah0.w, B0h.x, B0h.y);
                MMA16816(f0,f1,f2,f3, Ah0.x,Ah0.y,Ah0.z,Ah0.w, B1h.x, B1h.y);
                MMA16816(e0,e1,e2,e3, Al0.x,Al0.y,Al0.z,Al0.w, B0h.x, B0h.y);
                MMA16816(g0,g1,g2,g3, Al0.x,Al0.y,Al0.z,Al0.w, B1h.x, B1h.y);
                MMA16816(a0,a1,a2,a3, Ah1.x,Ah1.y,Ah1.z,Ah1.w, B0h.z, B0h.w);
                MMA16816(f0,f1,f2,f3, Ah1.x,Ah1.y,Ah1.z,Ah1.w, B1h.z, B1h.w);
                MMA16816(e0,e1,e2,e3, Al1.x,Al1.y,Al1.z,Al1.w, B0h.z, B0h.w);
                MMA16816(g0,g1,g2,g3, Al1.x,Al1.y,Al1.z,Al1.w, B1h.z, B1h.w);
                MMA16816(e0,e1,e2,e3, Ah0.x,Ah0.y,Ah0.z,Ah0.w, B0l.x, B0l.y);
                MMA16816(g0,g1,g2,g3, Ah0.x,Ah0.y,Ah0.z,Ah0.w, B1l.x, B1l.y);
                MMA16816(e0,e1,e2,e3, Ah1.x,Ah1.y,Ah1.z,Ah1.w, B0l.z, B0l.w);
                MMA16816(g0,g1,g2,g3, Ah1.x,Ah1.y,Ah1.z,Ah1.w, B1l.z, B1l.w);

                float4 w = WF4[(mt * 8 + nt) * 32 + lane];
                float sm0, sm1;
                sm0  = fmaf(fmaxf(a0 + e0, 0.0f), w.x, 0.0f);
                sm0  = fmaf(fmaxf(a1 + e1, 0.0f), w.y, sm0);
                sm0  = fmaf(fmaxf(a2 + e2, 0.0f), w.z, sm0);
                sm0  = fmaf(fmaxf(a3 + e3, 0.0f), w.w, sm0);
                sm1  = fmaf(fmaxf(f0 + g0, 0.0f), w.x, 0.0f);
                sm1  = fmaf(fmaxf(f1 + g1, 0.0f), w.y, sm1);
                sm1  = fmaf(fmaxf(f2 + g2, 0.0f), w.z, sm1);
                sm1  = fmaf(fmaxf(f3 + g3, 0.0f), w.w, sm1);
                if (mt < 4) { s00 += sm0; s10 += sm1; }
                else        { s01 += sm0; s11 += sm1; }
            }
        }
        // warp reduce; single writer per agg cell -> plain stores
        #pragma unroll
        for (int off = 16; off; off >>= 1) {
            s00 += __shfl_down_sync(0xffffffffu, s00, off);
            s01 += __shfl_down_sync(0xffffffffu, s01, off);
            s10 += __shfl_down_sync(0xffffffffu, s10, off);
            s11 += __shfl_down_sync(0xffffffffu, s11, off);
        }
        if (lane == 0) {
            aggs[ig0]      = s00;
            aggs[64 + ig0] = s01;
            aggs[ig1]      = s10;
            aggs[64 + ig1] = s11;
        }
    }
    __syncthreads();

    // ---- GRU tail: 2 inodes ----
    for (int il2 = 0; il2 < 2; il2++) {
        __syncthreads();
        if (t < 192) {
            float s = gbias[t];
            #pragma unroll 8
            for (int k = 0; k < 64; k++)
                s = fmaf(xrow[il2 * 64 + k], Kmat[k * 192 + t], s);
            xk1[t] = s;
        }
        __syncthreads();
        if (t < 64) {
            float z  = 1.0f / (1.0f + expf(-(xk1[t] + gbias[192 + t])));
            float r  = 1.0f / (1.0f + expf(-(xk1[64 + t] + gbias[256 + t])));
            float hh = tanhf(xk1[128 + t] + r * gbias[320 + t]);
            h1[t] = (1.0f - z) * hh;   // h was 0
        }
        __syncthreads();
        if (t < 192) {
            float s1g = gbias[t], s2g = gbias[192 + t];
            #pragma unroll 8
            for (int k = 0; k < 64; k++) {
                s1g = fmaf(aggs[il2 * 64 + k], Kmat[k * 192 + t], s1g);
                s2g = fmaf(h1[k],              Rmat[k * 192 + t], s2g);
            }
            xk2[t] = s1g; hk2[t] = s2g;
        }
        __syncthreads();
        if (t < 64) {
            float z  = 1.0f / (1.0f + expf(-(xk2[t] + hk2[t])));
            float r  = 1.0f / (1.0f + expf(-(xk2[64 + t] + hk2[64 + t])));
            float hh = tanhf(xk2[128 + t] + r * hk2[128 + t]);
            out[((size_t)(b * 64 + pair * 2 + il2)) * 64 + t] =
                z * h1[t] + (1.0f - z) * hh;
        }
    }
}

extern "C" void kernel_launch(void* const* d_in, const int* in_sizes, int n_in,
                              void* d_out, int out_size) {
    const float* nodes = (const float*)d_in[0];
    const float* edges = (const float*)d_in[1];
    const float* mask  = (const float*)d_in[2];
    const float* W_e   = (const float*)d_in[3];
    const float* b_e   = (const float*)d_in[4];
    const float* gk    = (const float*)d_in[5];
    const float* gr    = (const float*)d_in[6];
    const float* gb    = (const float*)d_in[7];
    float* out = (float*)d_out;

    conv_w_kernel<<<dim3(16, 4), 256>>>(W_e);

    cudaFuncSetAttribute(mp_mma_kernel,
                         cudaFuncAttributeMaxDynamicSharedMemorySize, SMEM_SZ);
    mp_mma_kernel<<<256, 256, SMEM_SZ>>>(nodes, edges, mask, b_e,
                                         gk, gr, gb, out);
}

// round 14
// speedup vs baseline: 4.2910x; 1.4820x over previous
#include <cuda_runtime.h>
#include <cuda_bf16.h>
#include <math.h>
#include <stdint.h>

// B=8, N=64, D=64, E=32. GEMM view: (32768 x 32) @ (32 x 4096), fused
// relu/mask/reduce epilogue + GRU tail. Single-pass TF32 mma.sync m16n8k8
// (11 mantissa bits; predicted rel_err ~2e-4 vs 1e-3 threshold, calibrated
// against measured bf16-3-term 6.6e-6). 3x fewer tensor MACs than the
// bf16 hi/lo-split kernels, and a register footprint that fits 128 regs
// without the spills that killed R9-R13.

typedef unsigned int u32;

// W fragment buffer: [ig(64)][nt(8)][half(2)][lane(32)] uint4
//   half 0 = ktiles 0,1 (x,y = b0,b1 of kt0; z,w = b0,b1 of kt1)
//   half 1 = ktiles 2,3
__device__ uint4 g_Wfrag4[32768];   // 512 KB

static __device__ __forceinline__ u32 tf32cvt(float v) {
    u32 r;
    asm("cvt.rna.tf32.f32 %0, %1;" : "=r"(r) : "f"(v));
    return r;
}

#define MMAT32(c0,c1,c2,c3,a0,a1,a2,a3,b0,b1) \
    asm volatile("mma.sync.aligned.m16n8k8.row.col.f32.tf32.tf32.f32 " \
        "{%0,%1,%2,%3},{%4,%5,%6,%7},{%8,%9},{%0,%1,%2,%3};" \
        : "+f"(c0),"+f"(c1),"+f"(c2),"+f"(c3) \
        : "r"(a0),"r"(a1),"r"(a2),"r"(a3),"r"(b0),"r"(b1))

// ---------------- converter: W_e -> tf32 fragments ----------------
__global__ void conv_w_kernel(const float* __restrict__ W_e) {
    int idx  = blockIdx.x * 256 + threadIdx.x;   // 0..32767, one uint4 each
    int lane = idx & 31;
    int half = (idx >> 5) & 1;
    int ntig = idx >> 6;                          // ig*8 + nt, 0..511
    int ncol = (ntig << 3) + (lane >> 2);         // global column
    int k0   = half * 16 + (lane & 3);
    uint4 v;
    v.x = tf32cvt(W_e[(size_t)k0 * 4096 + ncol]);          // kt even, b0
    v.y = tf32cvt(W_e[(size_t)(k0 + 4) * 4096 + ncol]);    // kt even, b1
    v.z = tf32cvt(W_e[(size_t)(k0 + 8) * 4096 + ncol]);    // kt odd,  b0
    v.w = tf32cvt(W_e[(size_t)(k0 + 12) * 4096 + ncol]);   // kt odd,  b1
    g_Wfrag4[idx] = v;
}

// ---------------- main kernel ----------------
// dynamic smem layout (bytes)
#define OFF_AF    0        // A frags: [mt(8)][kt(4)][lane(32)] uint4 = 16KB
#define OFF_WF    16384    // wt frags: [mt(8)][nt(8)][lane(32)] float4 = 32KB
#define OFF_AGGS  49152    // 128 f
#define OFF_XROW  49664    // 128 f
#define OFF_XK1   50176    // 192 f
#define OFF_H1    50944    // 64 f
#define OFF_XK2   51200    // 192 f
#define OFF_HK2   51968    // 192 f
#define SMEM_SZ   52736

__global__ __launch_bounds__(256, 2) void mp_mma_kernel(
    const float* __restrict__ nodes,   // (8,64,64)
    const float* __restrict__ edges,   // (8,4096,32)
    const float* __restrict__ mask,    // (8,4096,1)
    const float* __restrict__ b_e,     // (4096,)
    const float* __restrict__ Kmat,    // (64,192)
    const float* __restrict__ Rmat,    // (64,192)
    const float* __restrict__ gbias,   // (2,192)
    float* __restrict__ out)           // (8,64,64)
{
    extern __shared__ char sm[];
    u32*    AF   = (u32*)(sm + OFF_AF);
    uint4*  AF4  = (uint4*)(sm + OFF_AF);
    float4* WF4  = (float4*)(sm + OFF_WF);
    float*  aggs = (float*)(sm + OFF_AGGS);
    float*  xrow = (float*)(sm + OFF_XROW);
    float*  xk1  = (float*)(sm + OFF_XK1);
    float*  h1   = (float*)(sm + OFF_H1);
    float*  xk2  = (float*)(sm + OFF_XK2);
    float*  hk2  = (float*)(sm + OFF_HK2);

    const int t    = threadIdx.x;
    const int lane = t & 31;
    const int wid  = t >> 5;          // 0..7
    const int b    = blockIdx.x >> 5;
    const int pair = blockIdx.x & 31;

    if (t < 128)
        xrow[t] = nodes[((size_t)b * 64 + pair * 2 + (t >> 6)) * 64 + (t & 63)];

    // ---- A staging: edges rows -> tf32 fragment-major smem ----
    // m16n8k8 A frag: a0(r<8,k%8<4) a1(r>=8,k%8<4) a2(r<8,k%8>=4) a3(r>=8,k%8>=4)
    {
        int m = t >> 1, half = t & 1;
        int mt = m >> 4, r16 = m & 15;
        const float* ar = edges + ((size_t)(b * 4096 + pair * 128 + m)) * 32 + half * 16;
        float v[16];
        #pragma unroll
        for (int i = 0; i < 16; i += 4) {
            float4 x = *(const float4*)(ar + i);
            v[i] = x.x; v[i + 1] = x.y; v[i + 2] = x.z; v[i + 3] = x.w;
        }
        #pragma unroll
        for (int i = 0; i < 16; i++) {
            int k   = half * 16 + i;
            int kt  = k >> 3;
            int reg = (r16 >> 3) + 2 * ((k >> 2) & 1);
            int ln  = (r16 & 7) * 4 + (k & 3);
            AF[((mt * 4 + kt) * 32 + ln) * 4 + reg] = tf32cvt(v[i]);
        }
    }
    // ---- wt fragments: mask*nodes in fragment-major float4 ----
    for (int idx = t; idx < 2048; idx += 256) {
        int mt = idx >> 8, nt = (idx >> 5) & 7, ln = idx & 31;
        int rr = ln >> 2, q = ln & 3;
        int mrow = mt * 16 + rr;
        int c = nt * 8 + 2 * q;
        int il = mrow >> 6;
        int jn1 = mrow & 63, jn2 = (mrow + 8) & 63;
        float m1 = mask[(size_t)b * 4096 + (pair * 2 + il) * 64 + jn1];
        float m2 = mask[(size_t)b * 4096 + (pair * 2 + il) * 64 + jn2];
        float2 n1 = *(const float2*)(nodes + ((size_t)b * 64 + jn1) * 64 + c);
        float2 n2 = *(const float2*)(nodes + ((size_t)b * 64 + jn2) * 64 + c);
        float4 w; w.x = n1.x * m1; w.y = n1.y * m1; w.z = n2.x * m2; w.w = n2.y * m2;
        WF4[idx] = w;
    }
    __syncthreads();

    const int q = lane & 3;

    for (int igl = 0; igl < 8; igl++) {
        const int ig = wid * 8 + igl;

        // B fragments for all 8 nt (64 regs) + bias (16 regs)
        uint4 Bh[8], Bl[8];
        float2 bb[8];
        #pragma unroll
        for (int nt = 0; nt < 8; nt++) {
            Bh[nt] = g_Wfrag4[((ig * 8 + nt) * 2 + 0) * 32 + lane];
            Bl[nt] = g_Wfrag4[((ig * 8 + nt) * 2 + 1) * 32 + lane];
            bb[nt] = __ldg((const float2*)(b_e + ig * 64 + nt * 8 + 2 * q));
        }

        float s0 = 0.f, s1 = 0.f;

        #pragma unroll
        for (int mt = 0; mt < 8; mt++) {
            uint4 A0 = AF4[(mt * 4 + 0) * 32 + lane];
            uint4 A1 = AF4[(mt * 4 + 1) * 32 + lane];
            uint4 A2 = AF4[(mt * 4 + 2) * 32 + lane];
            uint4 A3 = AF4[(mt * 4 + 3) * 32 + lane];

            float sm_ = 0.f;
            #pragma unroll
            for (int nt = 0; nt < 8; nt++) {
                // two independent 2-MMA chains
                float c0 = bb[nt].x, c1 = bb[nt].y, c2 = bb[nt].x, c3 = bb[nt].y;
                float d0 = 0.f, d1 = 0.f, d2 = 0.f, d3 = 0.f;
                MMAT32(c0,c1,c2,c3, A0.x,A0.y,A0.z,A0.w, Bh[nt].x, Bh[nt].y);  // kt0
                MMAT32(d0,d1,d2,d3, A2.x,A2.y,A2.z,A2.w, Bl[nt].x, Bl[nt].y);  // kt2
                MMAT32(c0,c1,c2,c3, A1.x,A1.y,A1.z,A1.w, Bh[nt].z, Bh[nt].w);  // kt1
                MMAT32(d0,d1,d2,d3, A3.x,A3.y,A3.z,A3.w, Bl[nt].z, Bl[nt].w);  // kt3

                float4 w = WF4[(mt * 8 + nt) * 32 + lane];
                sm_ = fmaf(fmaxf(c0 + d0, 0.0f), w.x, sm_);
                sm_ = fmaf(fmaxf(c1 + d1, 0.0f), w.y, sm_);
                sm_ = fmaf(fmaxf(c2 + d2, 0.0f), w.z, sm_);
                sm_ = fmaf(fmaxf(c3 + d3, 0.0f), w.w, sm_);
            }
            if (mt < 4) s0 += sm_; else s1 += sm_;
        }
        // warp reduce; single writer per agg cell -> plain stores
        #pragma unroll
        for (int off = 16; off; off >>= 1) {
            s0 += __shfl_down_sync(0xffffffffu, s0, off);
            s1 += __shfl_down_sync(0xffffffffu, s1, off);
        }
        if (lane == 0) {
            aggs[ig]      = s0;
            aggs[64 + ig] = s1;
        }
    }
    __syncthreads();

    // ---- GRU tail: 2 inodes ----
    for (int il2 = 0; il2 < 2; il2++) {
        __syncthreads();
        if (t < 192) {
            float s = gbias[t];
            #pragma unroll 8
            for (int k = 0; k < 64; k++)
                s = fmaf(xrow[il2 * 64 + k], Kmat[k * 192 + t], s);
            xk1[t] = s;
        }
        __syncthreads();
        if (t < 64) {
            float z  = 1.0f / (1.0f + expf(-(xk1[t] + gbias[192 + t])));
            float r  = 1.0f / (1.0f + expf(-(xk1[64 + t] + gbias[256 + t])));
            float hh = tanhf(xk1[128 + t] + r * gbias[320 + t]);
            h1[t] = (1.0f - z) * hh;   // h was 0
        }
        __syncthreads();
        if (t < 192) {
            float s1g = gbias[t], s2g = gbias[192 + t];
            #pragma unroll 8
            for (int k = 0; k < 64; k++) {
                s1g = fmaf(aggs[il2 * 64 + k], Kmat[k * 192 + t], s1g);
                s2g = fmaf(h1[k],              Rmat[k * 192 + t], s2g);
            }
            xk2[t] = s1g; hk2[t] = s2g;
        }
        __syncthreads();
        if (t < 64) {
            float z  = 1.0f / (1.0f + expf(-(xk2[t] + hk2[t])));
            float r  = 1.0f / (1.0f + expf(-(xk2[64 + t] + hk2[64 + t])));
            float hh = tanhf(xk2[128 + t] + r * hk2[128 + t]);
            out[((size_t)(b * 64 + pair * 2 + il2)) * 64 + t] =
                z * h1[t] + (1.0f - z) * hh;
        }
    }
}

extern "C" void kernel_launch(void* const* d_in, const int* in_sizes, int n_in,
                              void* d_out, int out_size) {
    const float* nodes = (const float*)d_in[0];
    const float* edges = (const float*)d_in[1];
    const float* mask  = (const float*)d_in[2];
    const float* W_e   = (const float*)d_in[3];
    const float* b_e   = (const float*)d_in[4];
    const float* gk    = (const float*)d_in[5];
    const float* gr    = (const float*)d_in[6];
    const float* gb    = (const float*)d_in[7];
    float* out = (float*)d_out;

    conv_w_kernel<<<128, 256>>>(W_e);

    cudaFuncSetAttribute(mp_mma_kernel,
                         cudaFuncAttributeMaxDynamicSharedMemorySize, SMEM_SZ);
    mp_mma_kernel<<<256, 256, SMEM_SZ>>>(nodes, edges, mask, b_e,
                                         gk, gr, gb, out);
}